// round 2
// baseline (speedup 1.0000x reference)
#include <cuda_runtime.h>
#include <math.h>

// Problem constants
#define NB   4
#define C3   256
#define HW3  3136
#define C4   512
#define HW4  784
#define EPSV 1e-5f

// ---------------- scratch (static device globals; no allocation) ----------------
__device__ float d_gN3[NB * C3 * HW3];
__device__ float d_tN3[NB * C3 * HW3];
__device__ float d_gN4[NB * C4 * HW4];
__device__ float d_tN4[NB * C4 * HW4];
__device__ float d_cd3[(size_t)NB * HW3 * HW3];   // 157 MB
__device__ float d_cd4[(size_t)NB * HW4 * HW4];   // 9.8 MB
__device__ float d_c03[NB * HW3];
__device__ float d_b3 [NB * HW3];
__device__ float d_c04[NB * HW4];
__device__ float d_b4 [NB * HW4];
__device__ float d_rm3[NB * HW3];
__device__ float d_rm4[NB * HW4];

// ---------------- 1) normalize: center by mean(tar over C), L2-normalize over C --
// block = 128 threads = 4 C-partitions x 32 hw positions; grid = (ceil(HW/32), N)
__global__ __launch_bounds__(128) void normalize_kernel(
    const float* __restrict__ gen, const float* __restrict__ tar,
    float* __restrict__ gN, float* __restrict__ tN, int C, int HW)
{
    int n    = blockIdx.y;
    int lane = threadIdx.x & 31;
    int cp   = threadIdx.x >> 5;          // 0..3
    int hw   = blockIdx.x * 32 + lane;
    bool ok  = hw < HW;

    __shared__ float r1[4][32];
    __shared__ float r2[4][32];

    const float* gp = gen + (size_t)n * C * HW + hw;
    const float* tp = tar + (size_t)n * C * HW + hw;

    float s = 0.f;
    if (ok) {
        #pragma unroll 4
        for (int c = cp; c < C; c += 4) s += tp[(size_t)c * HW];
    }
    r1[cp][lane] = s;
    __syncthreads();
    float mean = (r1[0][lane] + r1[1][lane] + r1[2][lane] + r1[3][lane]) / (float)C;
    __syncthreads();

    float sg = 0.f, st = 0.f;
    if (ok) {
        #pragma unroll 4
        for (int c = cp; c < C; c += 4) {
            float g = gp[(size_t)c * HW] - mean;
            float t = tp[(size_t)c * HW] - mean;
            sg += g * g;
            st += t * t;
        }
    }
    r1[cp][lane] = sg;
    r2[cp][lane] = st;
    __syncthreads();
    float rg = 1.0f / sqrtf(r1[0][lane] + r1[1][lane] + r1[2][lane] + r1[3][lane]);
    float rt = 1.0f / sqrtf(r2[0][lane] + r2[1][lane] + r2[2][lane] + r2[3][lane]);

    if (ok) {
        float* go = gN + (size_t)n * C * HW + hw;
        float* to = tN + (size_t)n * C * HW + hw;
        #pragma unroll 4
        for (int c = cp; c < C; c += 4) {
            go[(size_t)c * HW] = (gp[(size_t)c * HW] - mean) * rg;
            to[(size_t)c * HW] = (tp[(size_t)c * HW] - mean) * rt;
        }
    }
}

// ---------------- 2) GEMM: cd[n][p][q] = (1 - sum_c tN[c][p]*gN[c][q]) / 2 -------
// A = tN viewed as (C x P), B = gN viewed as (C x Q).  128x128x8 tile, 8x8 microtile.
#define BM 128
#define BN 128
#define BKT 8

__global__ __launch_bounds__(256) void gemm_cd_kernel(
    const float* __restrict__ A, const float* __restrict__ B,
    float* __restrict__ CD, int C, int P, int Q)
{
    __shared__ float As[BKT][BM];
    __shared__ float Bs[BKT][BN];

    int n = blockIdx.z;
    const float* An = A + (size_t)n * C * P;
    const float* Bn = B + (size_t)n * C * Q;
    float*       Cn = CD + (size_t)n * P * Q;

    int tid = threadIdx.x;
    int tx = tid & 15, ty = tid >> 4;
    int row0 = blockIdx.y * BM;
    int col0 = blockIdx.x * BN;

    float acc[8][8];
    #pragma unroll
    for (int i = 0; i < 8; i++)
        #pragma unroll
        for (int j = 0; j < 8; j++) acc[i][j] = 0.f;

    for (int k0 = 0; k0 < C; k0 += BKT) {
        #pragma unroll
        for (int i = 0; i < 4; i++) {
            int e  = tid + i * 256;
            int kk = e >> 7;
            int mm = e & 127;
            int ar = row0 + mm;
            int bc = col0 + mm;
            As[kk][mm] = (ar < P) ? An[(size_t)(k0 + kk) * P + ar] : 0.f;
            Bs[kk][mm] = (bc < Q) ? Bn[(size_t)(k0 + kk) * Q + bc] : 0.f;
        }
        __syncthreads();

        #pragma unroll
        for (int kk = 0; kk < BKT; kk++) {
            float4 a0 = *(const float4*)&As[kk][ty * 8];
            float4 a1 = *(const float4*)&As[kk][ty * 8 + 4];
            float4 b0 = *(const float4*)&Bs[kk][tx * 8];
            float4 b1 = *(const float4*)&Bs[kk][tx * 8 + 4];
            float a[8] = {a0.x, a0.y, a0.z, a0.w, a1.x, a1.y, a1.z, a1.w};
            float b[8] = {b0.x, b0.y, b0.z, b0.w, b1.x, b1.y, b1.z, b1.w};
            #pragma unroll
            for (int i = 0; i < 8; i++)
                #pragma unroll
                for (int j = 0; j < 8; j++)
                    acc[i][j] = fmaf(a[i], b[j], acc[i][j]);
        }
        __syncthreads();
    }

    #pragma unroll
    for (int i = 0; i < 8; i++) {
        int r = row0 + ty * 8 + i;
        if (r < P) {
            #pragma unroll
            for (int j = 0; j < 8; j++) {
                int c = col0 + tx * 8 + j;
                if (c < Q)
                    Cn[(size_t)r * Q + c] = 0.5f * (1.0f - acc[i][j]);
            }
        }
    }
}

// ---------------- 3) column min over p -> c0_q = -2/(min + eps) ------------------
// block = 256 = 32 cols x 8 row-slices; grid = (ceil(Q/32), N)
__global__ __launch_bounds__(256) void colmin_kernel(
    const float* __restrict__ CD, float* __restrict__ c0, int P, int Q)
{
    int n    = blockIdx.y;
    int lane = threadIdx.x & 31;
    int rs   = threadIdx.x >> 5;
    int q    = blockIdx.x * 32 + lane;
    const float* Cn = CD + (size_t)n * P * Q;

    float m = __int_as_float(0x7f800000);  // +inf
    if (q < Q) {
        #pragma unroll 4
        for (int p = rs; p < P; p += 8)
            m = fminf(m, Cn[(size_t)p * Q + q]);
    }
    __shared__ float red[256];
    red[threadIdx.x] = m;
    __syncthreads();
    if (threadIdx.x < 128) red[threadIdx.x] = fminf(red[threadIdx.x], red[threadIdx.x + 128]);
    __syncthreads();
    if (threadIdx.x < 64)  red[threadIdx.x] = fminf(red[threadIdx.x], red[threadIdx.x + 64]);
    __syncthreads();
    if (threadIdx.x < 32) {
        float v = fminf(red[threadIdx.x], red[threadIdx.x + 32]);
        if (q < Q) c0[n * Q + q] = -2.0f / (v + EPSV);
    }
}

// ---------------- 4) column sum of e = exp(2 + c0*cd) -> b_q = 2 - log(S_q) ------
__global__ __launch_bounds__(256) void colsum_kernel(
    const float* __restrict__ CD, const float* __restrict__ c0,
    float* __restrict__ b, int P, int Q)
{
    int n    = blockIdx.y;
    int lane = threadIdx.x & 31;
    int rs   = threadIdx.x >> 5;
    int q    = blockIdx.x * 32 + lane;
    const float* Cn = CD + (size_t)n * P * Q;

    float s = 0.f;
    if (q < Q) {
        float c0q = c0[n * Q + q];
        #pragma unroll 4
        for (int p = rs; p < P; p += 8)
            s += __expf(fmaf(c0q, Cn[(size_t)p * Q + q], 2.0f));
    }
    __shared__ float red[256];
    red[threadIdx.x] = s;
    __syncthreads();
    if (threadIdx.x < 128) red[threadIdx.x] += red[threadIdx.x + 128];
    __syncthreads();
    if (threadIdx.x < 64)  red[threadIdx.x] += red[threadIdx.x + 64];
    __syncthreads();
    if (threadIdx.x < 32) {
        float S = red[threadIdx.x] + red[threadIdx.x + 32];
        if (q < Q) b[n * Q + q] = 2.0f - logf(S);
    }
}

// ---------------- 5) row max (log domain): rm_p = max_q (c0_q*cd + b_q) ----------
// block = 256 = 8 warps, 1 row per warp; grid = (ceil(P/8), N)
__global__ __launch_bounds__(256) void rowmax_kernel(
    const float* __restrict__ CD, const float* __restrict__ c0,
    const float* __restrict__ b, float* __restrict__ rm, int P, int Q)
{
    __shared__ float sc0[HW3];
    __shared__ float sb [HW3];

    int n    = blockIdx.y;
    int warp = threadIdx.x >> 5;
    int lane = threadIdx.x & 31;

    for (int i = threadIdx.x; i < Q; i += 256) {
        sc0[i] = c0[n * Q + i];
        sb[i]  = b [n * Q + i];
    }
    __syncthreads();

    int p = blockIdx.x * 8 + warp;
    if (p < P) {
        const float* row = CD + (size_t)n * P * Q + (size_t)p * Q;
        float m = -__int_as_float(0x7f800000);
        #pragma unroll 4
        for (int q = lane; q < Q; q += 32)
            m = fmaxf(m, fmaf(sc0[q], row[q], sb[q]));
        #pragma unroll
        for (int o = 16; o > 0; o >>= 1)
            m = fmaxf(m, __shfl_xor_sync(0xffffffffu, m, o));
        if (lane == 0) rm[n * P + p] = m;
    }
}

// ---------------- 6) final: sum_n -log(mean_p exp(rm)); combine layers -----------
__global__ __launch_bounds__(256) void final_kernel(
    const float* __restrict__ rm3, const float* __restrict__ rm4,
    float* __restrict__ out)
{
    __shared__ float red[256];
    int tid = threadIdx.x;
    float total = 0.f;

    for (int n = 0; n < NB; n++) {
        float s = 0.f;
        for (int p = tid; p < HW3; p += 256) s += expf(rm3[n * HW3 + p]);
        red[tid] = s;
        __syncthreads();
        for (int o = 128; o > 0; o >>= 1) {
            if (tid < o) red[tid] += red[tid + o];
            __syncthreads();
        }
        total += 0.5f * (-logf(red[0] / (float)HW3));
        __syncthreads();
    }
    for (int n = 0; n < NB; n++) {
        float s = 0.f;
        for (int p = tid; p < HW4; p += 256) s += expf(rm4[n * HW4 + p]);
        red[tid] = s;
        __syncthreads();
        for (int o = 128; o > 0; o >>= 1) {
            if (tid < o) red[tid] += red[tid + o];
            __syncthreads();
        }
        total += 1.0f * (-logf(red[0] / (float)HW4));
        __syncthreads();
    }
    if (tid == 0) out[0] = total;
}

// ---------------- launch ---------------------------------------------------------
extern "C" void kernel_launch(void* const* d_in, const int* in_sizes, int n_in,
                              void* d_out, int out_size)
{
    const float* gen3 = (const float*)d_in[0];
    const float* tar3 = (const float*)d_in[1];
    const float* gen4 = (const float*)d_in[2];
    const float* tar4 = (const float*)d_in[3];

    float *gN3, *tN3, *gN4, *tN4, *cd3, *cd4, *c03, *b3, *c04, *b4, *rm3, *rm4;
    cudaGetSymbolAddress((void**)&gN3, d_gN3);
    cudaGetSymbolAddress((void**)&tN3, d_tN3);
    cudaGetSymbolAddress((void**)&gN4, d_gN4);
    cudaGetSymbolAddress((void**)&tN4, d_tN4);
    cudaGetSymbolAddress((void**)&cd3, d_cd3);
    cudaGetSymbolAddress((void**)&cd4, d_cd4);
    cudaGetSymbolAddress((void**)&c03, d_c03);
    cudaGetSymbolAddress((void**)&b3,  d_b3);
    cudaGetSymbolAddress((void**)&c04, d_c04);
    cudaGetSymbolAddress((void**)&b4,  d_b4);
    cudaGetSymbolAddress((void**)&rm3, d_rm3);
    cudaGetSymbolAddress((void**)&rm4, d_rm4);

    // ---- layer 3 ----
    {
        dim3 gn((HW3 + 31) / 32, NB);
        normalize_kernel<<<gn, 128>>>(gen3, tar3, gN3, tN3, C3, HW3);
        dim3 gg((HW3 + BN - 1) / BN, (HW3 + BM - 1) / BM, NB);
        gemm_cd_kernel<<<gg, 256>>>(tN3, gN3, cd3, C3, HW3, HW3);
        dim3 gc((HW3 + 31) / 32, NB);
        colmin_kernel<<<gc, 256>>>(cd3, c03, HW3, HW3);
        colsum_kernel<<<gc, 256>>>(cd3, c03, b3, HW3, HW3);
        dim3 gr((HW3 + 7) / 8, NB);
        rowmax_kernel<<<gr, 256>>>(cd3, c03, b3, rm3, HW3, HW3);
    }
    // ---- layer 4 ----
    {
        dim3 gn((HW4 + 31) / 32, NB);
        normalize_kernel<<<gn, 128>>>(gen4, tar4, gN4, tN4, C4, HW4);
        dim3 gg((HW4 + BN - 1) / BN, (HW4 + BM - 1) / BM, NB);
        gemm_cd_kernel<<<gg, 256>>>(tN4, gN4, cd4, C4, HW4, HW4);
        dim3 gc((HW4 + 31) / 32, NB);
        colmin_kernel<<<gc, 256>>>(cd4, c04, HW4, HW4);
        colsum_kernel<<<gc, 256>>>(cd4, c04, b4, HW4, HW4);
        dim3 gr((HW4 + 7) / 8, NB);
        rowmax_kernel<<<gr, 256>>>(cd4, c04, b4, rm4, HW4, HW4);
    }

    final_kernel<<<1, 256>>>(rm3, rm4, (float*)d_out);
}

// round 4
// speedup vs baseline: 3.5079x; 3.5079x over previous
#include <cuda_runtime.h>
#include <cuda_bf16.h>
#include <cuda_fp16.h>
#include <math.h>
#include <stdint.h>

#define NB   4
#define C3   256
#define HW3  3136
#define HWP3 3200
#define C4   512
#define HW4  784
#define HWP4 896
#define SL3  56
#define RPS3 56
#define SL4  28
#define RPS4 28
#define EPSV 1e-5f
#define LOG2E 1.4426950408889634f
#define K2C   2.8853900817779268f   /* 2*log2(e) */

// ---------------- scratch ----------------
__device__ __nv_bfloat16 d_tT3[(size_t)NB * HWP3 * C3];
__device__ __nv_bfloat16 d_gT3[(size_t)NB * HWP3 * C3];
__device__ __nv_bfloat16 d_tT4[(size_t)NB * HWP4 * C4];
__device__ __nv_bfloat16 d_gT4[(size_t)NB * HWP4 * C4];
__device__ __half d_cd3[(size_t)NB * HW3 * HW3];
__device__ __half d_cd4[(size_t)NB * HW4 * HW4];
__device__ float d_mean[NB * HW3], d_rg[NB * HW3], d_rt[NB * HW3];
__device__ float d_pred[(size_t)NB * SL3 * HW3];
__device__ float d_c0e[NB * HW3], d_be[NB * HW3];
__device__ float d_rm3[NB * HW3], d_rm4[NB * HW4];

// ---------------- PTX helpers (baseline ISA only: sm_80-class) -------------------
__device__ __forceinline__ uint32_t smem_u32(const void* p) {
    uint32_t a;
    asm("{ .reg .u64 t; cvta.to.shared.u64 t, %1; cvt.u32.u64 %0, t; }" : "=r"(a) : "l"(p));
    return a;
}
__device__ __forceinline__ void cp16(uint32_t dst, const void* src) {
    asm volatile("cp.async.cg.shared.global [%0], [%1], 16;" :: "r"(dst), "l"(src));
}
#define CP_COMMIT() asm volatile("cp.async.commit_group;" ::: "memory")
#define CP_WAIT0()  asm volatile("cp.async.wait_group 0;" ::: "memory")
#define CP_WAIT1()  asm volatile("cp.async.wait_group 1;" ::: "memory")

__device__ __forceinline__ void ldm_x4(uint32_t* r, uint32_t addr) {
    asm volatile("ldmatrix.sync.aligned.m8n8.x4.shared.b16 {%0,%1,%2,%3}, [%4];"
        : "=r"(r[0]), "=r"(r[1]), "=r"(r[2]), "=r"(r[3]) : "r"(addr));
}
__device__ __forceinline__ void mma_bf16(float* d, const uint32_t* a, const uint32_t* b) {
    asm volatile(
        "mma.sync.aligned.m16n8k16.row.col.f32.bf16.bf16.f32 "
        "{%0,%1,%2,%3}, {%4,%5,%6,%7}, {%8,%9}, {%0,%1,%2,%3};"
        : "+f"(d[0]), "+f"(d[1]), "+f"(d[2]), "+f"(d[3])
        : "r"(a[0]), "r"(a[1]), "r"(a[2]), "r"(a[3]), "r"(b[0]), "r"(b[1]));
}

// ---------------- 1) stats: mean(tar|C), 1/||g-mu||, 1/||t-mu|| ------------------
__global__ __launch_bounds__(128) void stats_k(
    const float* __restrict__ g, const float* __restrict__ t,
    float* __restrict__ mean, float* __restrict__ rg, float* __restrict__ rt,
    int C, int HW)
{
    int n = blockIdx.y, lane = threadIdx.x & 31, cp = threadIdx.x >> 5;
    int hw = blockIdx.x * 32 + lane;
    bool ok = hw < HW;
    __shared__ float red[4][4][32];
    const float* gp = g + (size_t)n * C * HW + hw;
    const float* tp = t + (size_t)n * C * HW + hw;
    float st = 0, st2 = 0, sg = 0, sg2 = 0;
    if (ok) {
        #pragma unroll 4
        for (int c = cp; c < C; c += 4) {
            float tv = tp[(size_t)c * HW], gv = gp[(size_t)c * HW];
            st += tv; st2 += tv * tv; sg += gv; sg2 += gv * gv;
        }
    }
    red[0][cp][lane] = st; red[1][cp][lane] = st2;
    red[2][cp][lane] = sg; red[3][cp][lane] = sg2;
    __syncthreads();
    if (cp == 0 && ok) {
        st  = red[0][0][lane] + red[0][1][lane] + red[0][2][lane] + red[0][3][lane];
        st2 = red[1][0][lane] + red[1][1][lane] + red[1][2][lane] + red[1][3][lane];
        sg  = red[2][0][lane] + red[2][1][lane] + red[2][2][lane] + red[2][3][lane];
        sg2 = red[3][0][lane] + red[3][1][lane] + red[3][2][lane] + red[3][3][lane];
        float mu = st / (float)C;
        mean[n * HW + hw] = mu;
        rt[n * HW + hw] = rsqrtf(st2 - (float)C * mu * mu);
        rg[n * HW + hw] = rsqrtf(sg2 - 2.f * mu * sg + (float)C * mu * mu);
    }
}

// ---------------- 2) transpose+normalize+bf16: (C,HW) -> (HWpad,C) ---------------
__global__ __launch_bounds__(256) void trans_k(
    const float* __restrict__ g, const float* __restrict__ t,
    const float* __restrict__ mean, const float* __restrict__ rg, const float* __restrict__ rt,
    __nv_bfloat16* __restrict__ gT, __nv_bfloat16* __restrict__ tT,
    int C, int HW, int HWpad)
{
    __shared__ float sg[32][33], st[32][33];
    int n = blockIdx.z;
    int c0 = blockIdx.x * 32, hw0 = blockIdx.y * 32;
    int tx = threadIdx.x & 31, ty = threadIdx.x >> 5;
    int hw = hw0 + tx;
    float mu = 0.f, sgn = 0.f, stn = 0.f;
    if (hw < HW) {
        mu  = mean[n * HW + hw];
        sgn = rg[n * HW + hw];
        stn = rt[n * HW + hw];
    }
    const size_t ib = (size_t)n * C * HW;
    #pragma unroll
    for (int i = 0; i < 4; i++) {
        int c = c0 + ty + i * 8;
        float vg = 0.f, vt = 0.f;
        if (hw < HW) {
            vg = (g[ib + (size_t)c * HW + hw] - mu) * sgn;
            vt = (t[ib + (size_t)c * HW + hw] - mu) * stn;
        }
        sg[ty + i * 8][tx] = vg;
        st[ty + i * 8][tx] = vt;
    }
    __syncthreads();
    #pragma unroll
    for (int i = 0; i < 4; i++) {
        int hwo = hw0 + ty + i * 8;
        int c = c0 + tx;
        size_t o = ((size_t)n * HWpad + hwo) * C + c;
        gT[o] = __float2bfloat16(sg[tx][ty + i * 8]);
        tT[o] = __float2bfloat16(st[tx][ty + i * 8]);
    }
}

// ---------------- 3) mma.sync bf16 GEMM: cd = (1 - A.B^T)/2 -> fp16 --------------
// A = tT (Mpad x C) K-major bf16, B = gT (Npad x C) K-major bf16.
// CTA tile 128x128, 8 warps (4m x 2n), warp tile 32x64, K chunks of 64, cp.async
// double buffering, padded SMEM rows (64+8 bf16 = 144 B stride).
#define KCH   64
#define RSTR  144                 /* bytes per smem row */
#define ABUF  18432               /* 128 * 144 */
#define SMEMT (4 * ABUF)          /* A0 A1 B0 B1 */

__global__ __launch_bounds__(256, 1) void gemm_cd_mma(
    const __nv_bfloat16* __restrict__ A, const __nv_bfloat16* __restrict__ B,
    __half* __restrict__ CD, int C, int P, int Q, int Mpad, int Npad)
{
    extern __shared__ char dsm[];
    const int tid  = threadIdx.x;
    const int lane = tid & 31;
    const int wid  = tid >> 5;
    const int wm   = wid & 3;          // warp row (0..3)
    const int wn   = wid >> 2;         // warp col (0..1)
    const int n    = blockIdx.z;
    const int m0   = blockIdx.y * 128;
    const int n0   = blockIdx.x * 128;

    const uint32_t sbase = smem_u32(dsm);
    const uint32_t sA = sbase;
    const uint32_t sB = sbase + 2 * ABUF;

    const __nv_bfloat16* An = A + ((size_t)n * Mpad + m0) * C;
    const __nv_bfloat16* Bn = B + ((size_t)n * Npad + n0) * C;

    const int row_ld = tid >> 3;       // 0..31 (x8 iters -> 0..127 via +32)
    const int c16    = tid & 7;        // 16B chunk within 128B row

    float acc[2][8][4];
    #pragma unroll
    for (int mi = 0; mi < 2; mi++)
        #pragma unroll
        for (int ni = 0; ni < 8; ni++)
            #pragma unroll
            for (int e = 0; e < 4; e++) acc[mi][ni][e] = 0.f;

    const int nch = C >> 6;

    // chunk loader: 128 rows x 64 bf16 each for A and B
    auto load_chunk = [&](int c, int buf) {
        const __nv_bfloat16* Ak = An + c * KCH;
        const __nv_bfloat16* Bk = Bn + c * KCH;
        uint32_t da = sA + buf * ABUF + row_ld * RSTR + c16 * 16;
        uint32_t db = sB + buf * ABUF + row_ld * RSTR + c16 * 16;
        #pragma unroll
        for (int i = 0; i < 4; i++) {
            int r = row_ld + i * 32;
            cp16(da + i * 32 * RSTR, Ak + (size_t)r * C + c16 * 8);
            cp16(db + i * 32 * RSTR, Bk + (size_t)r * C + c16 * 8);
        }
    };

    load_chunk(0, 0);
    CP_COMMIT();

    for (int c = 0; c < nch; c++) {
        const int buf = c & 1;
        if (c + 1 < nch) {
            load_chunk(c + 1, (c + 1) & 1);
            CP_COMMIT();
            CP_WAIT1();
        } else {
            CP_WAIT0();
        }
        __syncthreads();

        const uint32_t bA = sA + buf * ABUF;
        const uint32_t bB = sB + buf * ABUF;
        // A frag addr: row = wm*32 + mi*16 + (lane&15), col halves via lane>>4
        const uint32_t aRow = (uint32_t)(wm * 32 + (lane & 15));
        const uint32_t aColH = (uint32_t)((lane >> 4) * 8);
        // B frag addr: row = wn*64 + nb*16 + (quad>>1)*8 + r8, col = (quad&1)*8
        const int quad = lane >> 3, r8 = lane & 7;
        const uint32_t bRow = (uint32_t)(wn * 64 + (quad >> 1) * 8 + r8);
        const uint32_t bColH = (uint32_t)((quad & 1) * 8);

        #pragma unroll
        for (int ks = 0; ks < 4; ks++) {
            const int k0 = ks * 16;
            uint32_t af[2][4];
            #pragma unroll
            for (int mi = 0; mi < 2; mi++)
                ldm_x4(af[mi], bA + (aRow + mi * 16) * RSTR + (k0 + aColH) * 2);
            uint32_t bf[4][4];
            #pragma unroll
            for (int nb = 0; nb < 4; nb++)
                ldm_x4(bf[nb], bB + (bRow + nb * 16) * RSTR + (k0 + bColH) * 2);
            #pragma unroll
            for (int mi = 0; mi < 2; mi++) {
                #pragma unroll
                for (int nb = 0; nb < 4; nb++) {
                    mma_bf16(acc[mi][nb * 2],     af[mi], &bf[nb][0]);
                    mma_bf16(acc[mi][nb * 2 + 1], af[mi], &bf[nb][2]);
                }
            }
        }
        __syncthreads();
    }

    // epilogue: cd = (1 - acc) / 2 as fp16
    const int gid = lane >> 2, t4 = lane & 3;
    __half* Cn = CD + (size_t)n * P * Q;
    #pragma unroll
    for (int mi = 0; mi < 2; mi++) {
        #pragma unroll
        for (int h = 0; h < 2; h++) {
            int r = m0 + wm * 32 + mi * 16 + h * 8 + gid;
            if (r < P) {
                __half* rp = Cn + (size_t)r * Q;
                #pragma unroll
                for (int ni = 0; ni < 8; ni++) {
                    int col = n0 + wn * 64 + ni * 8 + t4 * 2;
                    if (col < Q) {
                        float fa = 0.5f * (1.0f - acc[mi][ni][h * 2]);
                        float fb = 0.5f * (1.0f - acc[mi][ni][h * 2 + 1]);
                        *(__half2*)(rp + col) = __floats2half2_rn(fa, fb);
                    }
                }
            }
        }
    }
}

// ---------------- 4) partial column min over a row-slice -------------------------
__global__ __launch_bounds__(256) void colmin_k(
    const __half* __restrict__ cd, float* __restrict__ pout,
    int P, int Q, int rps, int nsl)
{
    int n = blockIdx.z, sl = blockIdx.y;
    int nq8 = Q >> 3;
    int q8 = blockIdx.x * 256 + threadIdx.x;
    if (q8 >= nq8) return;
    const uint4* base = (const uint4*)(cd + (size_t)n * P * Q) + q8;
    int r0 = sl * rps;
    __half2 m0 = __float2half2_rn(65504.f), m1 = m0, m2 = m0, m3 = m0;
    #pragma unroll 4
    for (int r = r0; r < r0 + rps; r++) {
        uint4 v = base[(size_t)r * nq8];
        m0 = __hmin2(m0, *(__half2*)&v.x);
        m1 = __hmin2(m1, *(__half2*)&v.y);
        m2 = __hmin2(m2, *(__half2*)&v.z);
        m3 = __hmin2(m3, *(__half2*)&v.w);
    }
    float2 f0 = __half22float2(m0), f1 = __half22float2(m1);
    float2 f2 = __half22float2(m2), f3 = __half22float2(m3);
    float* pw = pout + ((size_t)n * nsl + sl) * Q + q8 * 8;
    *(float4*)pw       = make_float4(f0.x, f0.y, f1.x, f1.y);
    *(float4*)(pw + 4) = make_float4(f2.x, f2.y, f3.x, f3.y);
}

// ---------------- 5) stage2 min -> c0e = -2*log2e/(div+eps) ----------------------
__global__ __launch_bounds__(256) void stage2_min_k(
    const float* __restrict__ pin, float* __restrict__ c0e, int Q, int nsl)
{
    int n = blockIdx.y;
    int q = blockIdx.x * 256 + threadIdx.x;
    if (q >= Q) return;
    float m = 3.4e38f;
    for (int s = 0; s < nsl; s++)
        m = fminf(m, pin[((size_t)n * nsl + s) * Q + q]);
    c0e[n * Q + q] = (-2.0f / (m + EPSV)) * LOG2E;
}

// ---------------- 6) partial column sum of exp2(c0e*cd + 2log2e) -----------------
__global__ __launch_bounds__(256) void colsum_k(
    const __half* __restrict__ cd, const float* __restrict__ c0e,
    float* __restrict__ pout, int P, int Q, int rps, int nsl)
{
    int n = blockIdx.z, sl = blockIdx.y;
    int nq8 = Q >> 3;
    int q8 = blockIdx.x * 256 + threadIdx.x;
    if (q8 >= nq8) return;
    const uint4* base = (const uint4*)(cd + (size_t)n * P * Q) + q8;
    float4 ca = *(const float4*)(c0e + n * Q + q8 * 8);
    float4 cb = *(const float4*)(c0e + n * Q + q8 * 8 + 4);
    int r0 = sl * rps;
    float s0 = 0, s1 = 0, s2 = 0, s3 = 0, s4 = 0, s5 = 0, s6 = 0, s7 = 0;
    #pragma unroll 2
    for (int r = r0; r < r0 + rps; r++) {
        uint4 v = base[(size_t)r * nq8];
        float2 f0 = __half22float2(*(__half2*)&v.x);
        float2 f1 = __half22float2(*(__half2*)&v.y);
        float2 f2 = __half22float2(*(__half2*)&v.z);
        float2 f3 = __half22float2(*(__half2*)&v.w);
        s0 += exp2f(fmaf(ca.x, f0.x, K2C));
        s1 += exp2f(fmaf(ca.y, f0.y, K2C));
        s2 += exp2f(fmaf(ca.z, f1.x, K2C));
        s3 += exp2f(fmaf(ca.w, f1.y, K2C));
        s4 += exp2f(fmaf(cb.x, f2.x, K2C));
        s5 += exp2f(fmaf(cb.y, f2.y, K2C));
        s6 += exp2f(fmaf(cb.z, f3.x, K2C));
        s7 += exp2f(fmaf(cb.w, f3.y, K2C));
    }
    float* pw = pout + ((size_t)n * nsl + sl) * Q + q8 * 8;
    *(float4*)pw       = make_float4(s0, s1, s2, s3);
    *(float4*)(pw + 4) = make_float4(s4, s5, s6, s7);
}

// ---------------- 7) stage2 sum -> be = 2log2e - log2(S) -------------------------
__global__ __launch_bounds__(256) void stage2_sum_k(
    const float* __restrict__ pin, float* __restrict__ be, int Q, int nsl)
{
    int n = blockIdx.y;
    int q = blockIdx.x * 256 + threadIdx.x;
    if (q >= Q) return;
    float s = 0.f;
    for (int sl = 0; sl < nsl; sl++)
        s += pin[((size_t)n * nsl + sl) * Q + q];
    be[n * Q + q] = K2C - log2f(s);
}

// ---------------- 8) row max: rm_p = max_q (c0e_q*cd + be_q) ---------------------
__global__ __launch_bounds__(256) void rowmax_k(
    const __half* __restrict__ cd, const float* __restrict__ c0e,
    const float* __restrict__ be, float* __restrict__ rm, int P, int Q)
{
    __shared__ float sc[HW3], sb[HW3];
    int n = blockIdx.y;
    for (int i = threadIdx.x; i < Q; i += 256) {
        sc[i] = c0e[n * Q + i];
        sb[i] = be[n * Q + i];
    }
    __syncthreads();
    int p = blockIdx.x * 8 + (threadIdx.x >> 5);
    int lane = threadIdx.x & 31;
    if (p >= P) return;
    const uint4* row = (const uint4*)(cd + (size_t)n * P * Q + (size_t)p * Q);
    int nq8 = Q >> 3;
    float m = -3.4e38f;
    for (int i = lane; i < nq8; i += 32) {
        uint4 v = row[i];
        int qb = i * 8;
        float2 f0 = __half22float2(*(__half2*)&v.x);
        float2 f1 = __half22float2(*(__half2*)&v.y);
        float2 f2 = __half22float2(*(__half2*)&v.z);
        float2 f3 = __half22float2(*(__half2*)&v.w);
        m = fmaxf(m, fmaf(sc[qb],     f0.x, sb[qb]));
        m = fmaxf(m, fmaf(sc[qb + 1], f0.y, sb[qb + 1]));
        m = fmaxf(m, fmaf(sc[qb + 2], f1.x, sb[qb + 2]));
        m = fmaxf(m, fmaf(sc[qb + 3], f1.y, sb[qb + 3]));
        m = fmaxf(m, fmaf(sc[qb + 4], f2.x, sb[qb + 4]));
        m = fmaxf(m, fmaf(sc[qb + 5], f2.y, sb[qb + 5]));
        m = fmaxf(m, fmaf(sc[qb + 6], f3.x, sb[qb + 6]));
        m = fmaxf(m, fmaf(sc[qb + 7], f3.y, sb[qb + 7]));
    }
    #pragma unroll
    for (int o = 16; o > 0; o >>= 1)
        m = fmaxf(m, __shfl_xor_sync(0xffffffffu, m, o));
    if (lane == 0) rm[n * P + p] = m;
}

// ---------------- 9) final -------------------------------------------------------
__global__ __launch_bounds__(256) void final_k(
    const float* __restrict__ rm3, const float* __restrict__ rm4,
    float* __restrict__ out)
{
    __shared__ float red[256];
    int tid = threadIdx.x;
    float total = 0.f;
    for (int n = 0; n < NB; n++) {
        float s = 0.f;
        for (int p = tid; p < HW3; p += 256) s += exp2f(rm3[n * HW3 + p]);
        red[tid] = s;
        __syncthreads();
        for (int o = 128; o > 0; o >>= 1) {
            if (tid < o) red[tid] += red[tid + o];
            __syncthreads();
        }
        total += 0.5f * (-logf(red[0] / (float)HW3));
        __syncthreads();
    }
    for (int n = 0; n < NB; n++) {
        float s = 0.f;
        for (int p = tid; p < HW4; p += 256) s += exp2f(rm4[n * HW4 + p]);
        red[tid] = s;
        __syncthreads();
        for (int o = 128; o > 0; o >>= 1) {
            if (tid < o) red[tid] += red[tid + o];
            __syncthreads();
        }
        total += 1.0f * (-logf(red[0] / (float)HW4));
        __syncthreads();
    }
    if (tid == 0) out[0] = total;
}

// ---------------- launch ---------------------------------------------------------
extern "C" void kernel_launch(void* const* d_in, const int* in_sizes, int n_in,
                              void* d_out, int out_size)
{
    const float* gen3 = (const float*)d_in[0];
    const float* tar3 = (const float*)d_in[1];
    const float* gen4 = (const float*)d_in[2];
    const float* tar4 = (const float*)d_in[3];

    __nv_bfloat16 *tT3, *gT3, *tT4, *gT4;
    __half *cd3, *cd4;
    float *mean, *rg, *rt, *pred, *c0e, *be, *rm3, *rm4;
    cudaGetSymbolAddress((void**)&tT3, d_tT3);
    cudaGetSymbolAddress((void**)&gT3, d_gT3);
    cudaGetSymbolAddress((void**)&tT4, d_tT4);
    cudaGetSymbolAddress((void**)&gT4, d_gT4);
    cudaGetSymbolAddress((void**)&cd3, d_cd3);
    cudaGetSymbolAddress((void**)&cd4, d_cd4);
    cudaGetSymbolAddress((void**)&mean, d_mean);
    cudaGetSymbolAddress((void**)&rg, d_rg);
    cudaGetSymbolAddress((void**)&rt, d_rt);
    cudaGetSymbolAddress((void**)&pred, d_pred);
    cudaGetSymbolAddress((void**)&c0e, d_c0e);
    cudaGetSymbolAddress((void**)&be, d_be);
    cudaGetSymbolAddress((void**)&rm3, d_rm3);
    cudaGetSymbolAddress((void**)&rm4, d_rm4);

    cudaFuncSetAttribute(gemm_cd_mma, cudaFuncAttributeMaxDynamicSharedMemorySize, SMEMT);

    // ---- layer 3 ----
    stats_k<<<dim3(HW3 / 32, NB), 128>>>(gen3, tar3, mean, rg, rt, C3, HW3);
    trans_k<<<dim3(C3 / 32, HWP3 / 32, NB), 256>>>(gen3, tar3, mean, rg, rt, gT3, tT3, C3, HW3, HWP3);
    gemm_cd_mma<<<dim3(HWP3 / 128, HWP3 / 128, NB), 256, SMEMT>>>(tT3, gT3, cd3, C3, HW3, HW3, HWP3, HWP3);
    colmin_k<<<dim3(2, SL3, NB), 256>>>(cd3, pred, HW3, HW3, RPS3, SL3);
    stage2_min_k<<<dim3((HW3 + 255) / 256, NB), 256>>>(pred, c0e, HW3, SL3);
    colsum_k<<<dim3(2, SL3, NB), 256>>>(cd3, c0e, pred, HW3, HW3, RPS3, SL3);
    stage2_sum_k<<<dim3((HW3 + 255) / 256, NB), 256>>>(pred, be, HW3, SL3);
    rowmax_k<<<dim3((HW3 + 7) / 8, NB), 256>>>(cd3, c0e, be, rm3, HW3, HW3);

    // ---- layer 4 ----
    stats_k<<<dim3((HW4 + 31) / 32, NB), 128>>>(gen4, tar4, mean, rg, rt, C4, HW4);
    trans_k<<<dim3(C4 / 32, HWP4 / 32, NB), 256>>>(gen4, tar4, mean, rg, rt, gT4, tT4, C4, HW4, HWP4);
    gemm_cd_mma<<<dim3(HWP4 / 128, HWP4 / 128, NB), 256, SMEMT>>>(tT4, gT4, cd4, C4, HW4, HW4, HWP4, HWP4);
    colmin_k<<<dim3(1, SL4, NB), 256>>>(cd4, pred, HW4, HW4, RPS4, SL4);
    stage2_min_k<<<dim3((HW4 + 255) / 256, NB), 256>>>(pred, c0e, HW4, SL4);
    colsum_k<<<dim3(1, SL4, NB), 256>>>(cd4, c0e, pred, HW4, HW4, RPS4, SL4);
    stage2_sum_k<<<dim3((HW4 + 255) / 256, NB), 256>>>(pred, be, HW4, SL4);
    rowmax_k<<<dim3((HW4 + 7) / 8, NB), 256>>>(cd4, c0e, be, rm4, HW4, HW4);

    final_k<<<1, 256>>>(rm3, rm4, (float*)d_out);
}

// round 5
// speedup vs baseline: 3.6401x; 1.0377x over previous
#include <cuda_runtime.h>
#include <cuda_bf16.h>
#include <cuda_fp16.h>
#include <math.h>
#include <stdint.h>

#define NB   4
#define C3   256
#define HW3  3136
#define HWP3 3200
#define C4   512
#define HW4  784
#define HWP4 896
#define EPSV 1e-5f
#define LOG2E 1.4426950408889634f
#define K2C   2.8853900817779268f   /* 2*log2(e) */

#define NSLT3 25    /* gemm row tiles layer3 */
#define NSLT4 7
#define RPSS  16    /* rows per slice, colsum */
#define NSLS3 196   /* 3136/16 */
#define NSLS4 49    /* 784/16 */

// ---------------- scratch ----------------
__device__ __nv_bfloat16 d_tT3[(size_t)NB * HWP3 * C3];
__device__ __nv_bfloat16 d_gT3[(size_t)NB * HWP3 * C3];
__device__ __nv_bfloat16 d_tT4[(size_t)NB * HWP4 * C4];
__device__ __nv_bfloat16 d_gT4[(size_t)NB * HWP4 * C4];
__device__ __half d_cd3[(size_t)NB * HW3 * HW3];
__device__ __half d_cd4[(size_t)NB * HW4 * HW4];
__device__ float d_mean[NB * HW3], d_rg[NB * HW3], d_rt[NB * HW3];
__device__ float d_pred[(size_t)NB * NSLS3 * HW3];
__device__ float d_c0e[NB * HW3], d_be[NB * HW3];
__device__ float d_rm3[NB * HW3], d_rm4[NB * HW4];

// ---------------- PTX helpers (baseline ISA: sm_80-class) ------------------------
__device__ __forceinline__ uint32_t smem_u32(const void* p) {
    uint32_t a;
    asm("{ .reg .u64 t; cvta.to.shared.u64 t, %1; cvt.u32.u64 %0, t; }" : "=r"(a) : "l"(p));
    return a;
}
__device__ __forceinline__ void cp16(uint32_t dst, const void* src) {
    asm volatile("cp.async.cg.shared.global [%0], [%1], 16;" :: "r"(dst), "l"(src));
}
#define CP_COMMIT() asm volatile("cp.async.commit_group;" ::: "memory")
#define CP_WAIT2()  asm volatile("cp.async.wait_group 2;" ::: "memory")

__device__ __forceinline__ void ldm_x4(uint32_t* r, uint32_t addr) {
    asm volatile("ldmatrix.sync.aligned.m8n8.x4.shared.b16 {%0,%1,%2,%3}, [%4];"
        : "=r"(r[0]), "=r"(r[1]), "=r"(r[2]), "=r"(r[3]) : "r"(addr));
}
__device__ __forceinline__ void mma_bf16(float* d, const uint32_t* a, const uint32_t* b) {
    asm volatile(
        "mma.sync.aligned.m16n8k16.row.col.f32.bf16.bf16.f32 "
        "{%0,%1,%2,%3}, {%4,%5,%6,%7}, {%8,%9}, {%0,%1,%2,%3};"
        : "+f"(d[0]), "+f"(d[1]), "+f"(d[2]), "+f"(d[3])
        : "r"(a[0]), "r"(a[1]), "r"(a[2]), "r"(a[3]), "r"(b[0]), "r"(b[1]));
}

// ---------------- 1) stats ------------------------------------------------------
__global__ __launch_bounds__(128) void stats_k(
    const float* __restrict__ g, const float* __restrict__ t,
    float* __restrict__ mean, float* __restrict__ rg, float* __restrict__ rt,
    int C, int HW)
{
    int n = blockIdx.y, lane = threadIdx.x & 31, cp = threadIdx.x >> 5;
    int hw = blockIdx.x * 32 + lane;
    bool ok = hw < HW;
    __shared__ float red[4][4][32];
    const float* gp = g + (size_t)n * C * HW + hw;
    const float* tp = t + (size_t)n * C * HW + hw;
    float st = 0, st2 = 0, sg = 0, sg2 = 0;
    if (ok) {
        #pragma unroll 4
        for (int c = cp; c < C; c += 4) {
            float tv = tp[(size_t)c * HW], gv = gp[(size_t)c * HW];
            st += tv; st2 += tv * tv; sg += gv; sg2 += gv * gv;
        }
    }
    red[0][cp][lane] = st; red[1][cp][lane] = st2;
    red[2][cp][lane] = sg; red[3][cp][lane] = sg2;
    __syncthreads();
    if (cp == 0 && ok) {
        st  = red[0][0][lane] + red[0][1][lane] + red[0][2][lane] + red[0][3][lane];
        st2 = red[1][0][lane] + red[1][1][lane] + red[1][2][lane] + red[1][3][lane];
        sg  = red[2][0][lane] + red[2][1][lane] + red[2][2][lane] + red[2][3][lane];
        sg2 = red[3][0][lane] + red[3][1][lane] + red[3][2][lane] + red[3][3][lane];
        float mu = st / (float)C;
        mean[n * HW + hw] = mu;
        rt[n * HW + hw] = rsqrtf(st2 - (float)C * mu * mu);
        rg[n * HW + hw] = rsqrtf(sg2 - 2.f * mu * sg + (float)C * mu * mu);
    }
}

// ---------------- 2) transpose+normalize+bf16 ------------------------------------
__global__ __launch_bounds__(256) void trans_k(
    const float* __restrict__ g, const float* __restrict__ t,
    const float* __restrict__ mean, const float* __restrict__ rg, const float* __restrict__ rt,
    __nv_bfloat16* __restrict__ gT, __nv_bfloat16* __restrict__ tT,
    int C, int HW, int HWpad)
{
    __shared__ float sg[32][33], st[32][33];
    int n = blockIdx.z;
    int c0 = blockIdx.x * 32, hw0 = blockIdx.y * 32;
    int tx = threadIdx.x & 31, ty = threadIdx.x >> 5;
    int hw = hw0 + tx;
    float mu = 0.f, sgn = 0.f, stn = 0.f;
    if (hw < HW) {
        mu  = mean[n * HW + hw];
        sgn = rg[n * HW + hw];
        stn = rt[n * HW + hw];
    }
    const size_t ib = (size_t)n * C * HW;
    #pragma unroll
    for (int i = 0; i < 4; i++) {
        int c = c0 + ty + i * 8;
        float vg = 0.f, vt = 0.f;
        if (hw < HW) {
            vg = (g[ib + (size_t)c * HW + hw] - mu) * sgn;
            vt = (t[ib + (size_t)c * HW + hw] - mu) * stn;
        }
        sg[ty + i * 8][tx] = vg;
        st[ty + i * 8][tx] = vt;
    }
    __syncthreads();
    #pragma unroll
    for (int i = 0; i < 4; i++) {
        int hwo = hw0 + ty + i * 8;
        int c = c0 + tx;
        size_t o = ((size_t)n * HWpad + hwo) * C + c;
        gT[o] = __float2bfloat16(sg[tx][ty + i * 8]);
        tT[o] = __float2bfloat16(st[tx][ty + i * 8]);
    }
}

// ---------------- 3) mma.sync bf16 GEMM + fused column-min -----------------------
// CTA 128x128, 8 warps (4m x 2n), warp tile 32x64, K chunks of 64, 4-stage cp.async.
#define KCH    64
#define RSTR   144
#define ABUF   18432              /* 128 * 144 */
#define STG    4
#define SMEMT  (STG * 2 * ABUF)   /* 147456 */

__global__ __launch_bounds__(256, 1) void gemm_cd_mma(
    const __nv_bfloat16* __restrict__ A, const __nv_bfloat16* __restrict__ B,
    __half* __restrict__ CD, float* __restrict__ pmin,
    int C, int P, int Q, int Mpad, int Npad, int nslT)
{
    extern __shared__ char dsm[];
    const int tid  = threadIdx.x;
    const int lane = tid & 31;
    const int wid  = tid >> 5;
    const int wm   = wid & 3;
    const int wn   = wid >> 2;
    const int n    = blockIdx.z;
    const int by   = blockIdx.y;
    const int m0   = by * 128;
    const int n0   = blockIdx.x * 128;

    const uint32_t sbase = smem_u32(dsm);
    const uint32_t sA = sbase;
    const uint32_t sB = sbase + STG * ABUF;

    const __nv_bfloat16* An = A + ((size_t)n * Mpad + m0) * C;
    const __nv_bfloat16* Bn = B + ((size_t)n * Npad + n0) * C;

    const int row_ld = tid >> 3;
    const int c16    = tid & 7;

    float acc[2][8][4];
    #pragma unroll
    for (int mi = 0; mi < 2; mi++)
        #pragma unroll
        for (int ni = 0; ni < 8; ni++)
            #pragma unroll
            for (int e = 0; e < 4; e++) acc[mi][ni][e] = 0.f;

    const int nch = C >> 6;

    auto load_chunk = [&](int c, int buf) {
        const __nv_bfloat16* Ak = An + c * KCH;
        const __nv_bfloat16* Bk = Bn + c * KCH;
        uint32_t da = sA + buf * ABUF + row_ld * RSTR + c16 * 16;
        uint32_t db = sB + buf * ABUF + row_ld * RSTR + c16 * 16;
        #pragma unroll
        for (int i = 0; i < 4; i++) {
            int r = row_ld + i * 32;
            cp16(da + i * 32 * RSTR, Ak + (size_t)r * C + c16 * 8);
            cp16(db + i * 32 * RSTR, Bk + (size_t)r * C + c16 * 8);
        }
    };

    #pragma unroll
    for (int s = 0; s < STG - 1; s++) {
        if (s < nch) load_chunk(s, s);
        CP_COMMIT();
    }

    const uint32_t aRow  = (uint32_t)(wm * 32 + (lane & 15));
    const uint32_t aColH = (uint32_t)((lane >> 4) * 8);
    const int quad = lane >> 3, r8 = lane & 7;
    const uint32_t bRow  = (uint32_t)(wn * 64 + (quad >> 1) * 8 + r8);
    const uint32_t bColH = (uint32_t)((quad & 1) * 8);

    for (int c = 0; c < nch; c++) {
        const int pf = c + STG - 1;
        if (pf < nch) load_chunk(pf, pf & (STG - 1));
        CP_COMMIT();
        CP_WAIT2();
        __syncthreads();

        const int buf = c & (STG - 1);
        const uint32_t bA = sA + buf * ABUF;
        const uint32_t bB = sB + buf * ABUF;

        #pragma unroll
        for (int ks = 0; ks < 4; ks++) {
            const int k0 = ks * 16;
            uint32_t af[2][4];
            #pragma unroll
            for (int mi = 0; mi < 2; mi++)
                ldm_x4(af[mi], bA + (aRow + mi * 16) * RSTR + (k0 + aColH) * 2);
            uint32_t bfr[4][4];
            #pragma unroll
            for (int nb = 0; nb < 4; nb++)
                ldm_x4(bfr[nb], bB + (bRow + nb * 16) * RSTR + (k0 + bColH) * 2);
            #pragma unroll
            for (int mi = 0; mi < 2; mi++) {
                #pragma unroll
                for (int nb = 0; nb < 4; nb++) {
                    mma_bf16(acc[mi][nb * 2],     af[mi], &bfr[nb][0]);
                    mma_bf16(acc[mi][nb * 2 + 1], af[mi], &bfr[nb][2]);
                }
            }
        }
        __syncthreads();
    }

    // ---- epilogue: cd = (1-acc)/2 -> fp16 store, plus per-CTA column min ----
    const int gid = lane >> 2, t4 = lane & 3;
    float cmin[16];
    #pragma unroll
    for (int i = 0; i < 16; i++) cmin[i] = INFINITY;
    __half* Cn = CD + (size_t)n * P * Q;
    #pragma unroll
    for (int mi = 0; mi < 2; mi++) {
        #pragma unroll
        for (int h = 0; h < 2; h++) {
            int r = m0 + wm * 32 + mi * 16 + h * 8 + gid;
            if (r < P) {
                __half* rp = Cn + (size_t)r * Q;
                #pragma unroll
                for (int ni = 0; ni < 8; ni++) {
                    int col = n0 + wn * 64 + ni * 8 + t4 * 2;
                    float fa = 0.5f * (1.0f - acc[mi][ni][h * 2]);
                    float fb = 0.5f * (1.0f - acc[mi][ni][h * 2 + 1]);
                    cmin[ni * 2]     = fminf(cmin[ni * 2], fa);
                    cmin[ni * 2 + 1] = fminf(cmin[ni * 2 + 1], fb);
                    if (col < Q)
                        *(__half2*)(rp + col) = __floats2half2_rn(fa, fb);
                }
            }
        }
    }
    // reduce over gid (lanes stride 4 share a column pair)
    #pragma unroll
    for (int o = 4; o < 32; o <<= 1)
        #pragma unroll
        for (int i = 0; i < 16; i++)
            cmin[i] = fminf(cmin[i], __shfl_xor_sync(0xffffffffu, cmin[i], o));

    float* smin = (float*)dsm;   // 4 x 128 floats (buffers no longer needed)
    if (gid == 0) {
        #pragma unroll
        for (int ni = 0; ni < 8; ni++) {
            smin[wm * 128 + wn * 64 + ni * 8 + t4 * 2]     = cmin[ni * 2];
            smin[wm * 128 + wn * 64 + ni * 8 + t4 * 2 + 1] = cmin[ni * 2 + 1];
        }
    }
    __syncthreads();
    if (tid < 128) {
        int colg = n0 + tid;
        if (colg < Q) {
            float m = fminf(fminf(smin[tid], smin[128 + tid]),
                            fminf(smin[256 + tid], smin[384 + tid]));
            pmin[((size_t)n * nslT + by) * Q + colg] = m;
        }
    }
}

// ---------------- 5) stage2 min -> c0e = -2*log2e/(div+eps) ----------------------
__global__ __launch_bounds__(256) void stage2_min_k(
    const float* __restrict__ pin, float* __restrict__ c0e, int Q, int nsl)
{
    int n = blockIdx.y;
    int q = blockIdx.x * 256 + threadIdx.x;
    if (q >= Q) return;
    float m = 3.4e38f;
    for (int s = 0; s < nsl; s++)
        m = fminf(m, pin[((size_t)n * nsl + s) * Q + q]);
    c0e[n * Q + q] = (-2.0f / (m + EPSV)) * LOG2E;
}

// ---------------- 6) partial column sum of exp2(c0e*cd + 2log2e) -----------------
__global__ __launch_bounds__(256) void colsum_k(
    const __half* __restrict__ cd, const float* __restrict__ c0e,
    float* __restrict__ pout, int P, int Q, int rps, int nsl)
{
    int n = blockIdx.z, sl = blockIdx.y;
    int nq8 = Q >> 3;
    int q8 = blockIdx.x * 256 + threadIdx.x;
    if (q8 >= nq8) return;
    const uint4* base = (const uint4*)(cd + (size_t)n * P * Q) + q8;
    float4 ca = *(const float4*)(c0e + n * Q + q8 * 8);
    float4 cb = *(const float4*)(c0e + n * Q + q8 * 8 + 4);
    int r0 = sl * rps;
    float s0 = 0, s1 = 0, s2 = 0, s3 = 0, s4 = 0, s5 = 0, s6 = 0, s7 = 0;
    #pragma unroll 4
    for (int r = r0; r < r0 + rps; r++) {
        uint4 v = base[(size_t)r * nq8];
        float2 f0 = __half22float2(*(__half2*)&v.x);
        float2 f1 = __half22float2(*(__half2*)&v.y);
        float2 f2 = __half22float2(*(__half2*)&v.z);
        float2 f3 = __half22float2(*(__half2*)&v.w);
        s0 += exp2f(fmaf(ca.x, f0.x, K2C));
        s1 += exp2f(fmaf(ca.y, f0.y, K2C));
        s2 += exp2f(fmaf(ca.z, f1.x, K2C));
        s3 += exp2f(fmaf(ca.w, f1.y, K2C));
        s4 += exp2f(fmaf(cb.x, f2.x, K2C));
        s5 += exp2f(fmaf(cb.y, f2.y, K2C));
        s6 += exp2f(fmaf(cb.z, f3.x, K2C));
        s7 += exp2f(fmaf(cb.w, f3.y, K2C));
    }
    float* pw = pout + ((size_t)n * nsl + sl) * Q + q8 * 8;
    *(float4*)pw       = make_float4(s0, s1, s2, s3);
    *(float4*)(pw + 4) = make_float4(s4, s5, s6, s7);
}

// ---------------- 7) stage2 sum -> be = 2log2e - log2(S) -------------------------
__global__ __launch_bounds__(256) void stage2_sum_k(
    const float* __restrict__ pin, float* __restrict__ be, int Q, int nsl)
{
    int n = blockIdx.y;
    int q = blockIdx.x * 256 + threadIdx.x;
    if (q >= Q) return;
    float s = 0.f;
    for (int sl = 0; sl < nsl; sl++)
        s += pin[((size_t)n * nsl + sl) * Q + q];
    be[n * Q + q] = K2C - log2f(s);
}

// ---------------- 8) row max: rm_p = max_q (c0e_q*cd + be_q) ---------------------
__global__ __launch_bounds__(256) void rowmax_k(
    const __half* __restrict__ cd, const float* __restrict__ c0e,
    const float* __restrict__ be, float* __restrict__ rm, int P, int Q)
{
    __shared__ float sc[HW3], sb[HW3];
    int n = blockIdx.y;
    for (int i = threadIdx.x; i < Q; i += 256) {
        sc[i] = c0e[n * Q + i];
        sb[i] = be[n * Q + i];
    }
    __syncthreads();
    int p = blockIdx.x * 8 + (threadIdx.x >> 5);
    int lane = threadIdx.x & 31;
    if (p >= P) return;
    const uint4* row = (const uint4*)(cd + (size_t)n * P * Q + (size_t)p * Q);
    int nq8 = Q >> 3;
    float m = -3.4e38f;
    for (int i = lane; i < nq8; i += 32) {
        uint4 v = row[i];
        int qb = i * 8;
        float2 f0 = __half22float2(*(__half2*)&v.x);
        float2 f1 = __half22float2(*(__half2*)&v.y);
        float2 f2 = __half22float2(*(__half2*)&v.z);
        float2 f3 = __half22float2(*(__half2*)&v.w);
        m = fmaxf(m, fmaf(sc[qb],     f0.x, sb[qb]));
        m = fmaxf(m, fmaf(sc[qb + 1], f0.y, sb[qb + 1]));
        m = fmaxf(m, fmaf(sc[qb + 2], f1.x, sb[qb + 2]));
        m = fmaxf(m, fmaf(sc[qb + 3], f1.y, sb[qb + 3]));
        m = fmaxf(m, fmaf(sc[qb + 4], f2.x, sb[qb + 4]));
        m = fmaxf(m, fmaf(sc[qb + 5], f2.y, sb[qb + 5]));
        m = fmaxf(m, fmaf(sc[qb + 6], f3.x, sb[qb + 6]));
        m = fmaxf(m, fmaf(sc[qb + 7], f3.y, sb[qb + 7]));
    }
    #pragma unroll
    for (int o = 16; o > 0; o >>= 1)
        m = fmaxf(m, __shfl_xor_sync(0xffffffffu, m, o));
    if (lane == 0) rm[n * P + p] = m;
}

// ---------------- 9) final -------------------------------------------------------
__global__ __launch_bounds__(256) void final_k(
    const float* __restrict__ rm3, const float* __restrict__ rm4,
    float* __restrict__ out)
{
    __shared__ float red[256];
    int tid = threadIdx.x;
    float total = 0.f;
    for (int n = 0; n < NB; n++) {
        float s = 0.f;
        for (int p = tid; p < HW3; p += 256) s += exp2f(rm3[n * HW3 + p]);
        red[tid] = s;
        __syncthreads();
        for (int o = 128; o > 0; o >>= 1) {
            if (tid < o) red[tid] += red[tid + o];
            __syncthreads();
        }
        total += 0.5f * (-logf(red[0] / (float)HW3));
        __syncthreads();
    }
    for (int n = 0; n < NB; n++) {
        float s = 0.f;
        for (int p = tid; p < HW4; p += 256) s += exp2f(rm4[n * HW4 + p]);
        red[tid] = s;
        __syncthreads();
        for (int o = 128; o > 0; o >>= 1) {
            if (tid < o) red[tid] += red[tid + o];
            __syncthreads();
        }
        total += 1.0f * (-logf(red[0] / (float)HW4));
        __syncthreads();
    }
    if (tid == 0) out[0] = total;
}

// ---------------- launch ---------------------------------------------------------
extern "C" void kernel_launch(void* const* d_in, const int* in_sizes, int n_in,
                              void* d_out, int out_size)
{
    const float* gen3 = (const float*)d_in[0];
    const float* tar3 = (const float*)d_in[1];
    const float* gen4 = (const float*)d_in[2];
    const float* tar4 = (const float*)d_in[3];

    __nv_bfloat16 *tT3, *gT3, *tT4, *gT4;
    __half *cd3, *cd4;
    float *mean, *rg, *rt, *pred, *c0e, *be, *rm3, *rm4;
    cudaGetSymbolAddress((void**)&tT3, d_tT3);
    cudaGetSymbolAddress((void**)&gT3, d_gT3);
    cudaGetSymbolAddress((void**)&tT4, d_tT4);
    cudaGetSymbolAddress((void**)&gT4, d_gT4);
    cudaGetSymbolAddress((void**)&cd3, d_cd3);
    cudaGetSymbolAddress((void**)&cd4, d_cd4);
    cudaGetSymbolAddress((void**)&mean, d_mean);
    cudaGetSymbolAddress((void**)&rg, d_rg);
    cudaGetSymbolAddress((void**)&rt, d_rt);
    cudaGetSymbolAddress((void**)&pred, d_pred);
    cudaGetSymbolAddress((void**)&c0e, d_c0e);
    cudaGetSymbolAddress((void**)&be, d_be);
    cudaGetSymbolAddress((void**)&rm3, d_rm3);
    cudaGetSymbolAddress((void**)&rm4, d_rm4);

    cudaFuncSetAttribute(gemm_cd_mma, cudaFuncAttributeMaxDynamicSharedMemorySize, SMEMT);

    // ---- layer 3 ----
    stats_k<<<dim3(HW3 / 32, NB), 128>>>(gen3, tar3, mean, rg, rt, C3, HW3);
    trans_k<<<dim3(C3 / 32, HWP3 / 32, NB), 256>>>(gen3, tar3, mean, rg, rt, gT3, tT3, C3, HW3, HWP3);
    gemm_cd_mma<<<dim3(HWP3 / 128, HWP3 / 128, NB), 256, SMEMT>>>(
        tT3, gT3, cd3, pred, C3, HW3, HW3, HWP3, HWP3, NSLT3);
    stage2_min_k<<<dim3((HW3 + 255) / 256, NB), 256>>>(pred, c0e, HW3, NSLT3);
    colsum_k<<<dim3(2, NSLS3, NB), 256>>>(cd3, c0e, pred, HW3, HW3, RPSS, NSLS3);
    stage2_sum_k<<<dim3((HW3 + 255) / 256, NB), 256>>>(pred, be, HW3, NSLS3);
    rowmax_k<<<dim3((HW3 + 7) / 8, NB), 256>>>(cd3, c0e, be, rm3, HW3, HW3);

    // ---- layer 4 ----
    stats_k<<<dim3((HW4 + 31) / 32, NB), 128>>>(gen4, tar4, mean, rg, rt, C4, HW4);
    trans_k<<<dim3(C4 / 32, HWP4 / 32, NB), 256>>>(gen4, tar4, mean, rg, rt, gT4, tT4, C4, HW4, HWP4);
    gemm_cd_mma<<<dim3(HWP4 / 128, HWP4 / 128, NB), 256, SMEMT>>>(
        tT4, gT4, cd4, pred, C4, HW4, HW4, HWP4, HWP4, NSLT4);
    stage2_min_k<<<dim3((HW4 + 255) / 256, NB), 256>>>(pred, c0e, HW4, NSLT4);
    colsum_k<<<dim3(1, NSLS4, NB), 256>>>(cd4, c0e, pred, HW4, HW4, RPSS, NSLS4);
    stage2_sum_k<<<dim3((HW4 + 255) / 256, NB), 256>>>(pred, be, HW4, NSLS4);
    rowmax_k<<<dim3((HW4 + 7) / 8, NB), 256>>>(cd4, c0e, be, rm4, HW4, HW4);

    final_k<<<1, 256>>>(rm3, rm4, (float*)d_out);
}

// round 6
// speedup vs baseline: 4.0505x; 1.1128x over previous
#include <cuda_runtime.h>
#include <cuda_bf16.h>
#include <cuda_fp16.h>
#include <math.h>
#include <stdint.h>

#define NB   4
#define C3   256
#define HW3  3136
#define HWP3 3200
#define C4   512
#define HW4  784
#define HWP4 896
#define EPSV 1e-5f
#define LOG2E 1.4426950408889634f
#define K2C   2.8853900817779268f   /* 2*log2(e) */

#define NSLT3 25    /* gemm row tiles layer3 */
#define NSLT4 7
#define RPSS  16    /* rows per slice, colsum */
#define NSLS3 196   /* 3136/16 */
#define NSLS4 49    /* 784/16 */

// ---------------- scratch ----------------
__device__ __nv_bfloat16 d_tT3[(size_t)NB * HWP3 * C3];
__device__ __nv_bfloat16 d_gT3[(size_t)NB * HWP3 * C3];
__device__ __nv_bfloat16 d_tT4[(size_t)NB * HWP4 * C4];
__device__ __nv_bfloat16 d_gT4[(size_t)NB * HWP4 * C4];
__device__ __half d_cd3[(size_t)NB * HW3 * HW3];
__device__ __half d_cd4[(size_t)NB * HW4 * HW4];
__device__ float d_mean[NB * HW3], d_rg[NB * HW3], d_rt[NB * HW3];
__device__ float d_pred[(size_t)NB * NSLS3 * HW3];
__device__ float d_c0e[NB * HW3], d_be[NB * HW3];
__device__ float d_rm3[NB * HW3], d_rm4[NB * HW4];

// ---------------- PTX helpers (baseline ISA: sm_80-class) ------------------------
__device__ __forceinline__ uint32_t smem_u32(const void* p) {
    uint32_t a;
    asm("{ .reg .u64 t; cvta.to.shared.u64 t, %1; cvt.u32.u64 %0, t; }" : "=r"(a) : "l"(p));
    return a;
}
__device__ __forceinline__ void cp16(uint32_t dst, const void* src) {
    asm volatile("cp.async.cg.shared.global [%0], [%1], 16;" :: "r"(dst), "l"(src));
}
#define CP_COMMIT() asm volatile("cp.async.commit_group;" ::: "memory")
#define CP_WAITG2() asm volatile("cp.async.wait_group 2;" ::: "memory")

__device__ __forceinline__ void ldm_x4(uint32_t* r, uint32_t addr) {
    asm volatile("ldmatrix.sync.aligned.m8n8.x4.shared.b16 {%0,%1,%2,%3}, [%4];"
        : "=r"(r[0]), "=r"(r[1]), "=r"(r[2]), "=r"(r[3]) : "r"(addr));
}
__device__ __forceinline__ void mma_bf16(float* d, const uint32_t* a, const uint32_t* b) {
    asm volatile(
        "mma.sync.aligned.m16n8k16.row.col.f32.bf16.bf16.f32 "
        "{%0,%1,%2,%3}, {%4,%5,%6,%7}, {%8,%9}, {%0,%1,%2,%3};"
        : "+f"(d[0]), "+f"(d[1]), "+f"(d[2]), "+f"(d[3])
        : "r"(a[0]), "r"(a[1]), "r"(a[2]), "r"(a[3]), "r"(b[0]), "r"(b[1]));
}

// ---------------- 1) stats ------------------------------------------------------
__global__ __launch_bounds__(128) void stats_k(
    const float* __restrict__ g, const float* __restrict__ t,
    float* __restrict__ mean, float* __restrict__ rg, float* __restrict__ rt,
    int C, int HW)
{
    int n = blockIdx.y, lane = threadIdx.x & 31, cp = threadIdx.x >> 5;
    int hw = blockIdx.x * 32 + lane;
    bool ok = hw < HW;
    __shared__ float red[4][4][32];
    const float* gp = g + (size_t)n * C * HW + hw;
    const float* tp = t + (size_t)n * C * HW + hw;
    float st = 0, st2 = 0, sg = 0, sg2 = 0;
    if (ok) {
        #pragma unroll 4
        for (int c = cp; c < C; c += 4) {
            float tv = tp[(size_t)c * HW], gv = gp[(size_t)c * HW];
            st += tv; st2 += tv * tv; sg += gv; sg2 += gv * gv;
        }
    }
    red[0][cp][lane] = st; red[1][cp][lane] = st2;
    red[2][cp][lane] = sg; red[3][cp][lane] = sg2;
    __syncthreads();
    if (cp == 0 && ok) {
        st  = red[0][0][lane] + red[0][1][lane] + red[0][2][lane] + red[0][3][lane];
        st2 = red[1][0][lane] + red[1][1][lane] + red[1][2][lane] + red[1][3][lane];
        sg  = red[2][0][lane] + red[2][1][lane] + red[2][2][lane] + red[2][3][lane];
        sg2 = red[3][0][lane] + red[3][1][lane] + red[3][2][lane] + red[3][3][lane];
        float mu = st / (float)C;
        mean[n * HW + hw] = mu;
        rt[n * HW + hw] = rsqrtf(st2 - (float)C * mu * mu);
        rg[n * HW + hw] = rsqrtf(sg2 - 2.f * mu * sg + (float)C * mu * mu);
    }
}

// ---------------- 2) transpose+normalize+bf16 ------------------------------------
__global__ __launch_bounds__(256) void trans_k(
    const float* __restrict__ g, const float* __restrict__ t,
    const float* __restrict__ mean, const float* __restrict__ rg, const float* __restrict__ rt,
    __nv_bfloat16* __restrict__ gT, __nv_bfloat16* __restrict__ tT,
    int C, int HW, int HWpad)
{
    __shared__ float sg[32][33], st[32][33];
    int n = blockIdx.z;
    int c0 = blockIdx.x * 32, hw0 = blockIdx.y * 32;
    int tx = threadIdx.x & 31, ty = threadIdx.x >> 5;
    int hw = hw0 + tx;
    float mu = 0.f, sgn = 0.f, stn = 0.f;
    if (hw < HW) {
        mu  = mean[n * HW + hw];
        sgn = rg[n * HW + hw];
        stn = rt[n * HW + hw];
    }
    const size_t ib = (size_t)n * C * HW;
    #pragma unroll
    for (int i = 0; i < 4; i++) {
        int c = c0 + ty + i * 8;
        float vg = 0.f, vt = 0.f;
        if (hw < HW) {
            vg = (g[ib + (size_t)c * HW + hw] - mu) * sgn;
            vt = (t[ib + (size_t)c * HW + hw] - mu) * stn;
        }
        sg[ty + i * 8][tx] = vg;
        st[ty + i * 8][tx] = vt;
    }
    __syncthreads();
    #pragma unroll
    for (int i = 0; i < 4; i++) {
        int hwo = hw0 + ty + i * 8;
        int c = c0 + tx;
        size_t o = ((size_t)n * HWpad + hwo) * C + c;
        gT[o] = __float2bfloat16(sg[tx][ty + i * 8]);
        tT[o] = __float2bfloat16(st[tx][ty + i * 8]);
    }
}

// ---------------- 3) mma.sync bf16 GEMM + fused column-min -----------------------
// CTA 128x128, 8 warps (4m x 2n), warp tile 32x64, K chunks of 64, 3-stage cp.async,
// 2 CTAs/SM (4 warps per SMSP for latency hiding).
#define KCH    64
#define RSTR   144
#define ABUF   18432              /* 128 * 144 */
#define STG    3
#define SMEMT  (STG * 2 * ABUF)   /* 110592 */

__global__ __launch_bounds__(256, 2) void gemm_cd_mma(
    const __nv_bfloat16* __restrict__ A, const __nv_bfloat16* __restrict__ B,
    __half* __restrict__ CD, float* __restrict__ pmin,
    int C, int P, int Q, int Mpad, int Npad, int nslT)
{
    extern __shared__ char dsm[];
    const int tid  = threadIdx.x;
    const int lane = tid & 31;
    const int wid  = tid >> 5;
    const int wm   = wid & 3;
    const int wn   = wid >> 2;
    const int n    = blockIdx.z;
    const int by   = blockIdx.y;
    const int m0   = by * 128;
    const int n0   = blockIdx.x * 128;

    const uint32_t sbase = smem_u32(dsm);
    const uint32_t sA = sbase;
    const uint32_t sB = sbase + STG * ABUF;

    const __nv_bfloat16* An = A + ((size_t)n * Mpad + m0) * C;
    const __nv_bfloat16* Bn = B + ((size_t)n * Npad + n0) * C;

    const int row_ld = tid >> 3;
    const int c16    = tid & 7;

    float acc[2][8][4];
    #pragma unroll
    for (int mi = 0; mi < 2; mi++)
        #pragma unroll
        for (int ni = 0; ni < 8; ni++)
            #pragma unroll
            for (int e = 0; e < 4; e++) acc[mi][ni][e] = 0.f;

    const int nch = C >> 6;

    auto load_chunk = [&](int c, int buf) {
        const __nv_bfloat16* Ak = An + c * KCH;
        const __nv_bfloat16* Bk = Bn + c * KCH;
        uint32_t da = sA + buf * ABUF + row_ld * RSTR + c16 * 16;
        uint32_t db = sB + buf * ABUF + row_ld * RSTR + c16 * 16;
        #pragma unroll
        for (int i = 0; i < 4; i++) {
            int r = row_ld + i * 32;
            cp16(da + i * 32 * RSTR, Ak + (size_t)r * C + c16 * 8);
            cp16(db + i * 32 * RSTR, Bk + (size_t)r * C + c16 * 8);
        }
    };

    #pragma unroll
    for (int s = 0; s < STG - 1; s++) {
        if (s < nch) load_chunk(s, s);
        CP_COMMIT();
    }

    const uint32_t aRow  = (uint32_t)(wm * 32 + (lane & 15));
    const uint32_t aColH = (uint32_t)((lane >> 4) * 8);
    const int quad = lane >> 3, r8 = lane & 7;
    const uint32_t bRow  = (uint32_t)(wn * 64 + (quad >> 1) * 8 + r8);
    const uint32_t bColH = (uint32_t)((quad & 1) * 8);

    int buf = 0;
    for (int c = 0; c < nch; c++) {
        const int pf = c + STG - 1;
        if (pf < nch) load_chunk(pf, (pf >= STG) ? pf - STG * (pf / STG) : pf);
        CP_COMMIT();
        CP_WAITG2();
        __syncthreads();

        const uint32_t bA = sA + buf * ABUF;
        const uint32_t bB = sB + buf * ABUF;

        #pragma unroll
        for (int ks = 0; ks < 4; ks++) {
            const int k0 = ks * 16;
            uint32_t af[2][4];
            #pragma unroll
            for (int mi = 0; mi < 2; mi++)
                ldm_x4(af[mi], bA + (aRow + mi * 16) * RSTR + (k0 + aColH) * 2);
            uint32_t bfr[4][4];
            #pragma unroll
            for (int nb = 0; nb < 4; nb++)
                ldm_x4(bfr[nb], bB + (bRow + nb * 16) * RSTR + (k0 + bColH) * 2);
            #pragma unroll
            for (int mi = 0; mi < 2; mi++) {
                #pragma unroll
                for (int nb = 0; nb < 4; nb++) {
                    mma_bf16(acc[mi][nb * 2],     af[mi], &bfr[nb][0]);
                    mma_bf16(acc[mi][nb * 2 + 1], af[mi], &bfr[nb][2]);
                }
            }
        }
        __syncthreads();
        buf = (buf == STG - 1) ? 0 : buf + 1;
    }

    // ---- epilogue: cd = (1-acc)/2 -> fp16 store, plus per-CTA column min ----
    const int gid = lane >> 2, t4 = lane & 3;
    float cmin[16];
    #pragma unroll
    for (int i = 0; i < 16; i++) cmin[i] = INFINITY;
    __half* Cn = CD + (size_t)n * P * Q;
    #pragma unroll
    for (int mi = 0; mi < 2; mi++) {
        #pragma unroll
        for (int h = 0; h < 2; h++) {
            int r = m0 + wm * 32 + mi * 16 + h * 8 + gid;
            if (r < P) {
                __half* rp = Cn + (size_t)r * Q;
                #pragma unroll
                for (int ni = 0; ni < 8; ni++) {
                    int col = n0 + wn * 64 + ni * 8 + t4 * 2;
                    float fa = 0.5f * (1.0f - acc[mi][ni][h * 2]);
                    float fb = 0.5f * (1.0f - acc[mi][ni][h * 2 + 1]);
                    cmin[ni * 2]     = fminf(cmin[ni * 2], fa);
                    cmin[ni * 2 + 1] = fminf(cmin[ni * 2 + 1], fb);
                    if (col < Q)
                        *(__half2*)(rp + col) = __floats2half2_rn(fa, fb);
                }
            }
        }
    }
    #pragma unroll
    for (int o = 4; o < 32; o <<= 1)
        #pragma unroll
        for (int i = 0; i < 16; i++)
            cmin[i] = fminf(cmin[i], __shfl_xor_sync(0xffffffffu, cmin[i], o));

    float* smin = (float*)dsm;
    if (gid == 0) {
        #pragma unroll
        for (int ni = 0; ni < 8; ni++) {
            smin[wm * 128 + wn * 64 + ni * 8 + t4 * 2]     = cmin[ni * 2];
            smin[wm * 128 + wn * 64 + ni * 8 + t4 * 2 + 1] = cmin[ni * 2 + 1];
        }
    }
    __syncthreads();
    if (tid < 128) {
        int colg = n0 + tid;
        if (colg < Q) {
            float m = fminf(fminf(smin[tid], smin[128 + tid]),
                            fminf(smin[256 + tid], smin[384 + tid]));
            pmin[((size_t)n * nslT + by) * Q + colg] = m;
        }
    }
}

// ---------------- 5) stage2 min -> c0e = -2*log2e/(div+eps) ----------------------
__global__ __launch_bounds__(256) void stage2_min_k(
    const float* __restrict__ pin, float* __restrict__ c0e, int Q, int nsl)
{
    int n = blockIdx.y;
    int q = blockIdx.x * 256 + threadIdx.x;
    if (q >= Q) return;
    float m = 3.4e38f;
    #pragma unroll 5
    for (int s = 0; s < nsl; s++)
        m = fminf(m, pin[((size_t)n * nsl + s) * Q + q]);
    c0e[n * Q + q] = (-2.0f / (m + EPSV)) * LOG2E;
}

// ---------------- 6) partial column sum of exp2(c0e*cd + 2log2e) -----------------
__global__ __launch_bounds__(256) void colsum_k(
    const __half* __restrict__ cd, const float* __restrict__ c0e,
    float* __restrict__ pout, int P, int Q, int rps, int nsl)
{
    int n = blockIdx.z, sl = blockIdx.y;
    int nq8 = Q >> 3;
    int q8 = blockIdx.x * 256 + threadIdx.x;
    if (q8 >= nq8) return;
    const uint4* base = (const uint4*)(cd + (size_t)n * P * Q) + q8;
    float4 ca = *(const float4*)(c0e + n * Q + q8 * 8);
    float4 cb = *(const float4*)(c0e + n * Q + q8 * 8 + 4);
    int r0 = sl * rps;
    float s0 = 0, s1 = 0, s2 = 0, s3 = 0, s4 = 0, s5 = 0, s6 = 0, s7 = 0;
    #pragma unroll 4
    for (int r = r0; r < r0 + rps; r++) {
        uint4 v = base[(size_t)r * nq8];
        float2 f0 = __half22float2(*(__half2*)&v.x);
        float2 f1 = __half22float2(*(__half2*)&v.y);
        float2 f2 = __half22float2(*(__half2*)&v.z);
        float2 f3 = __half22float2(*(__half2*)&v.w);
        s0 += exp2f(fmaf(ca.x, f0.x, K2C));
        s1 += exp2f(fmaf(ca.y, f0.y, K2C));
        s2 += exp2f(fmaf(ca.z, f1.x, K2C));
        s3 += exp2f(fmaf(ca.w, f1.y, K2C));
        s4 += exp2f(fmaf(cb.x, f2.x, K2C));
        s5 += exp2f(fmaf(cb.y, f2.y, K2C));
        s6 += exp2f(fmaf(cb.z, f3.x, K2C));
        s7 += exp2f(fmaf(cb.w, f3.y, K2C));
    }
    float* pw = pout + ((size_t)n * nsl + sl) * Q + q8 * 8;
    *(float4*)pw       = make_float4(s0, s1, s2, s3);
    *(float4*)(pw + 4) = make_float4(s4, s5, s6, s7);
}

// ---------------- 7) stage2 sum -> be = 2log2e - log2(S) -------------------------
__global__ __launch_bounds__(256) void stage2_sum_k(
    const float* __restrict__ pin, float* __restrict__ be, int Q, int nsl)
{
    int n = blockIdx.y;
    int q = blockIdx.x * 256 + threadIdx.x;
    if (q >= Q) return;
    float s = 0.f;
    #pragma unroll 7
    for (int sl = 0; sl < nsl; sl++)
        s += pin[((size_t)n * nsl + sl) * Q + q];
    be[n * Q + q] = K2C - log2f(s);
}

// ---------------- 8) row max: rm_p = max_q (c0e_q*cd + be_q) ---------------------
__global__ __launch_bounds__(256) void rowmax_k(
    const __half* __restrict__ cd, const float* __restrict__ c0e,
    const float* __restrict__ be, float* __restrict__ rm, int P, int Q)
{
    __shared__ float sc[HW3], sb[HW3];
    int n = blockIdx.y;
    for (int i = threadIdx.x; i < Q; i += 256) {
        sc[i] = c0e[n * Q + i];
        sb[i] = be[n * Q + i];
    }
    __syncthreads();
    int p = blockIdx.x * 8 + (threadIdx.x >> 5);
    int lane = threadIdx.x & 31;
    if (p >= P) return;
    const uint4* row = (const uint4*)(cd + (size_t)n * P * Q + (size_t)p * Q);
    int nq8 = Q >> 3;
    float m = -3.4e38f;
    for (int i = lane; i < nq8; i += 32) {
        uint4 v = row[i];
        int qb = i * 8;
        float2 f0 = __half22float2(*(__half2*)&v.x);
        float2 f1 = __half22float2(*(__half2*)&v.y);
        float2 f2 = __half22float2(*(__half2*)&v.z);
        float2 f3 = __half22float2(*(__half2*)&v.w);
        m = fmaxf(m, fmaf(sc[qb],     f0.x, sb[qb]));
        m = fmaxf(m, fmaf(sc[qb + 1], f0.y, sb[qb + 1]));
        m = fmaxf(m, fmaf(sc[qb + 2], f1.x, sb[qb + 2]));
        m = fmaxf(m, fmaf(sc[qb + 3], f1.y, sb[qb + 3]));
        m = fmaxf(m, fmaf(sc[qb + 4], f2.x, sb[qb + 4]));
        m = fmaxf(m, fmaf(sc[qb + 5], f2.y, sb[qb + 5]));
        m = fmaxf(m, fmaf(sc[qb + 6], f3.x, sb[qb + 6]));
        m = fmaxf(m, fmaf(sc[qb + 7], f3.y, sb[qb + 7]));
    }
    #pragma unroll
    for (int o = 16; o > 0; o >>= 1)
        m = fmaxf(m, __shfl_xor_sync(0xffffffffu, m, o));
    if (lane == 0) rm[n * P + p] = m;
}

// ---------------- 9) final -------------------------------------------------------
__global__ __launch_bounds__(256) void final_k(
    const float* __restrict__ rm3, const float* __restrict__ rm4,
    float* __restrict__ out)
{
    __shared__ float red[256];
    int tid = threadIdx.x;
    float total = 0.f;
    for (int n = 0; n < NB; n++) {
        float s = 0.f;
        for (int p = tid; p < HW3; p += 256) s += exp2f(rm3[n * HW3 + p]);
        red[tid] = s;
        __syncthreads();
        for (int o = 128; o > 0; o >>= 1) {
            if (tid < o) red[tid] += red[tid + o];
            __syncthreads();
        }
        total += 0.5f * (-logf(red[0] / (float)HW3));
        __syncthreads();
    }
    for (int n = 0; n < NB; n++) {
        float s = 0.f;
        for (int p = tid; p < HW4; p += 256) s += exp2f(rm4[n * HW4 + p]);
        red[tid] = s;
        __syncthreads();
        for (int o = 128; o > 0; o >>= 1) {
            if (tid < o) red[tid] += red[tid + o];
            __syncthreads();
        }
        total += 1.0f * (-logf(red[0] / (float)HW4));
        __syncthreads();
    }
    if (tid == 0) out[0] = total;
}

// ---------------- launch ---------------------------------------------------------
extern "C" void kernel_launch(void* const* d_in, const int* in_sizes, int n_in,
                              void* d_out, int out_size)
{
    const float* gen3 = (const float*)d_in[0];
    const float* tar3 = (const float*)d_in[1];
    const float* gen4 = (const float*)d_in[2];
    const float* tar4 = (const float*)d_in[3];

    __nv_bfloat16 *tT3, *gT3, *tT4, *gT4;
    __half *cd3, *cd4;
    float *mean, *rg, *rt, *pred, *c0e, *be, *rm3, *rm4;
    cudaGetSymbolAddress((void**)&tT3, d_tT3);
    cudaGetSymbolAddress((void**)&gT3, d_gT3);
    cudaGetSymbolAddress((void**)&tT4, d_tT4);
    cudaGetSymbolAddress((void**)&gT4, d_gT4);
    cudaGetSymbolAddress((void**)&cd3, d_cd3);
    cudaGetSymbolAddress((void**)&cd4, d_cd4);
    cudaGetSymbolAddress((void**)&mean, d_mean);
    cudaGetSymbolAddress((void**)&rg, d_rg);
    cudaGetSymbolAddress((void**)&rt, d_rt);
    cudaGetSymbolAddress((void**)&pred, d_pred);
    cudaGetSymbolAddress((void**)&c0e, d_c0e);
    cudaGetSymbolAddress((void**)&be, d_be);
    cudaGetSymbolAddress((void**)&rm3, d_rm3);
    cudaGetSymbolAddress((void**)&rm4, d_rm4);

    cudaFuncSetAttribute(gemm_cd_mma, cudaFuncAttributeMaxDynamicSharedMemorySize, SMEMT);

    // ---- layer 3 ----
    stats_k<<<dim3(HW3 / 32, NB), 128>>>(gen3, tar3, mean, rg, rt, C3, HW3);
    trans_k<<<dim3(C3 / 32, HWP3 / 32, NB), 256>>>(gen3, tar3, mean, rg, rt, gT3, tT3, C3, HW3, HWP3);
    gemm_cd_mma<<<dim3(HWP3 / 128, HWP3 / 128, NB), 256, SMEMT>>>(
        tT3, gT3, cd3, pred, C3, HW3, HW3, HWP3, HWP3, NSLT3);
    stage2_min_k<<<dim3((HW3 + 255) / 256, NB), 256>>>(pred, c0e, HW3, NSLT3);
    colsum_k<<<dim3(2, NSLS3, NB), 256>>>(cd3, c0e, pred, HW3, HW3, RPSS, NSLS3);
    stage2_sum_k<<<dim3((HW3 + 255) / 256, NB), 256>>>(pred, be, HW3, NSLS3);
    rowmax_k<<<dim3((HW3 + 7) / 8, NB), 256>>>(cd3, c0e, be, rm3, HW3, HW3);

    // ---- layer 4 ----
    stats_k<<<dim3((HW4 + 31) / 32, NB), 128>>>(gen4, tar4, mean, rg, rt, C4, HW4);
    trans_k<<<dim3(C4 / 32, HWP4 / 32, NB), 256>>>(gen4, tar4, mean, rg, rt, gT4, tT4, C4, HW4, HWP4);
    gemm_cd_mma<<<dim3(HWP4 / 128, HWP4 / 128, NB), 256, SMEMT>>>(
        tT4, gT4, cd4, pred, C4, HW4, HW4, HWP4, HWP4, NSLT4);
    stage2_min_k<<<dim3((HW4 + 255) / 256, NB), 256>>>(pred, c0e, HW4, NSLT4);
    colsum_k<<<dim3(1, NSLS4, NB), 256>>>(cd4, c0e, pred, HW4, HW4, RPSS, NSLS4);
    stage2_sum_k<<<dim3((HW4 + 255) / 256, NB), 256>>>(pred, be, HW4, NSLS4);
    rowmax_k<<<dim3((HW4 + 7) / 8, NB), 256>>>(cd4, c0e, be, rm4, HW4, HW4);

    final_k<<<1, 256>>>(rm3, rm4, (float*)d_out);
}